// round 6
// baseline (speedup 1.0000x reference)
#include <cuda_runtime.h>
#include <cuda_bf16.h>
#include <math.h>

// ---------------- Problem constants ----------------
#define BATCH   16384
#define N_CAT   26
#define N_CONT  13
#define EDIM    128
#define VOCAB   100000
#define N_PAIRS 351            // 27*26/2
#define TOP_IN  479            // 351 + 128
#define TOP_IN_PAD 480

// ---------------- Scratch (device globals; allocation-free) ----------------
__device__ float g_h1[BATCH * 512];
__device__ float g_h2[BATCH * 256];
__device__ float g_dense[BATCH * EDIM];
__device__ float g_x[BATCH * TOP_IN_PAD];
__device__ float g_t1[BATCH * 1024];
__device__ float g_t2[BATCH * 1024];
__device__ float g_t3[BATCH * 512];
__device__ float g_t4[BATCH * 256];
__device__ float g_Wt1p[TOP_IN_PAD * 1024];
__device__ int   g_idx_is64;    // 1 if cat_idx buffer is int64, 0 if int32

// ---------------- cat_idx dtype detection ---------------------------------
// If the buffer is int64 (values < 100000 << 2^31, little-endian), every odd
// 32-bit word is 0. If it is int32 (uniform in [0,100000)), odd words are
// nonzero with overwhelming probability over 4096 samples.
__global__ void idx_reset_kernel() { g_idx_is64 = 1; }

__global__ void idx_detect_kernel(const int* __restrict__ cat_raw) {
    int i = blockIdx.x * 256 + threadIdx.x;      // sample index
    // look at odd words of the first 4096 64-bit slots (both interpretations
    // stay within the smaller int32 buffer: 8192 ints = 32 KB < 1.7 MB)
    int w = cat_raw[2 * i + 1];
    if (w != 0) g_idx_is64 = 0;                  // int32 data detected
}

// ---------------- Wt1 zero-pad (479x1024 -> 480x1024) ----------------
__global__ void pad_wt1_kernel(const float* __restrict__ Wt1) {
    int i = blockIdx.x * 256 + threadIdx.x;
    if (i >= TOP_IN_PAD * 1024) return;
    int r = i >> 10;           // /1024
    int c = i & 1023;
    g_Wt1p[i] = (r < TOP_IN) ? Wt1[r * 1024 + c] : 0.0f;
}

// ---------------- Bottom MLP layer 1: (B,13) @ (13,512) + b, relu ----------
__global__ void bottom1_kernel(const float* __restrict__ x,
                               const float* __restrict__ W,
                               const float* __restrict__ b) {
    __shared__ float xs[N_CONT];
    int batch = blockIdx.x;
    int n = threadIdx.x;
    if (n < N_CONT) xs[n] = x[batch * N_CONT + n];
    __syncthreads();
    float acc = b[n];
#pragma unroll
    for (int k = 0; k < N_CONT; k++)
        acc += xs[k] * W[k * 512 + n];
    g_h1[(size_t)batch * 512 + n] = fmaxf(acc, 0.0f);
}

// ---------------- Generic fp32 SGEMM: C = relu(A @ B + bias) ---------------
// A: M x K row-major, stride lda (floats). B: K x N row-major. C: M x N.
// Requires: M%128==0, N%128==0, K%8==0, lda%4==0.
#define BM 128
#define BN 128
#define BKK 8
#define TM 8
#define TN 8

template<bool RELU>
__global__ __launch_bounds__(256, 2)
void sgemm_bias_act(const float* __restrict__ A, const float* __restrict__ B,
                    const float* __restrict__ bias, float* __restrict__ C,
                    int N, int K, int lda) {
    __shared__ float As[BKK][BM];
    __shared__ float Bs[BKK][BN];

    const int tid = threadIdx.x;
    const int bx = blockIdx.x;   // N tile
    const int by = blockIdx.y;   // M tile

    const int tx = tid & 15;     // 16 threads in N
    const int ty = tid >> 4;     // 16 threads in M

    const int a_row = tid >> 1;
    const int a_col = (tid & 1) * 4;
    const int b_row = tid >> 5;
    const int b_col = (tid & 31) * 4;

    const float* Aptr = A + (size_t)(by * BM) * lda;
    const float* Bptr = B + bx * BN;

    float acc[TM][TN];
#pragma unroll
    for (int i = 0; i < TM; i++)
#pragma unroll
        for (int j = 0; j < TN; j++) acc[i][j] = 0.0f;

    for (int k0 = 0; k0 < K; k0 += BKK) {
        float4 av = *(const float4*)(Aptr + (size_t)a_row * lda + (k0 + a_col));
        As[a_col + 0][a_row] = av.x;
        As[a_col + 1][a_row] = av.y;
        As[a_col + 2][a_row] = av.z;
        As[a_col + 3][a_row] = av.w;
        float4 bv = *(const float4*)(Bptr + (size_t)(k0 + b_row) * N + b_col);
        *(float4*)&Bs[b_row][b_col] = bv;
        __syncthreads();

#pragma unroll
        for (int kk = 0; kk < BKK; kk++) {
            float ar[TM], br[TN];
#pragma unroll
            for (int i = 0; i < TM; i++) ar[i] = As[kk][ty * TM + i];
#pragma unroll
            for (int j = 0; j < TN; j++) br[j] = Bs[kk][tx * TN + j];
#pragma unroll
            for (int i = 0; i < TM; i++)
#pragma unroll
                for (int j = 0; j < TN; j++)
                    acc[i][j] = fmaf(ar[i], br[j], acc[i][j]);
        }
        __syncthreads();
    }

    const int row0 = by * BM + ty * TM;
    const int col0 = bx * BN + tx * TN;
    float bvals[TN];
#pragma unroll
    for (int j = 0; j < TN; j++) bvals[j] = bias[col0 + j];

#pragma unroll
    for (int i = 0; i < TM; i++) {
#pragma unroll
        for (int j4 = 0; j4 < TN; j4 += 4) {
            float4 v;
            v.x = acc[i][j4 + 0] + bvals[j4 + 0];
            v.y = acc[i][j4 + 1] + bvals[j4 + 1];
            v.z = acc[i][j4 + 2] + bvals[j4 + 2];
            v.w = acc[i][j4 + 3] + bvals[j4 + 3];
            if (RELU) {
                v.x = fmaxf(v.x, 0.0f); v.y = fmaxf(v.y, 0.0f);
                v.z = fmaxf(v.z, 0.0f); v.w = fmaxf(v.w, 0.0f);
            }
            *(float4*)(C + (size_t)(row0 + i) * N + col0 + j4) = v;
        }
    }
}

// ---------------- Gather + pairwise interaction ---------------------------
// One block (256 threads) per batch row. Reads cat_idx as int32 or int64
// depending on the runtime-detected flag; all indices clamped to [0,VOCAB).
__global__ __launch_bounds__(256)
void interact_kernel(const void* __restrict__ cat_idx,
                     const float* __restrict__ emb) {
    __shared__ float Zs[27][EDIM];
    __shared__ int idxs[N_CAT];

    const int b = blockIdx.x;
    const int tid = threadIdx.x;
    const int lane = tid & 31;
    const int warp = tid >> 5;   // 0..7

    if (tid < N_CAT) {
        long long v;
        if (g_idx_is64) {
            v = ((const long long*)cat_idx)[(size_t)b * N_CAT + tid];
        } else {
            v = (long long)((const int*)cat_idx)[(size_t)b * N_CAT + tid];
        }
        if (v < 0) v = 0;
        if (v >= VOCAB) v = VOCAB - 1;
        idxs[tid] = (int)v;
    }
    __syncthreads();

    // Gather: 27*128 = 3456 elements, 256 threads
    for (int i = tid; i < 27 * EDIM; i += 256) {
        int r = i >> 7;          // /128
        int c = i & 127;
        float v;
        if (r < N_CAT) {
            size_t off = (size_t)r * (VOCAB * EDIM) + (size_t)idxs[r] * EDIM + c;
            v = emb[off];
        } else {
            v = g_dense[(size_t)b * EDIM + c];
        }
        Zs[r][c] = v;
    }
    __syncthreads();

    float* xrow = g_x + (size_t)b * TOP_IN_PAD;

    // 351 pairs split across 8 warps
    for (int p = warp; p < N_PAIRS; p += 8) {
        int i = 0, rem = p;
        while (rem >= (N_CAT - i)) { rem -= (N_CAT - i); i++; }
        int j = i + 1 + rem;

        float s = 0.0f;
#pragma unroll
        for (int q = 0; q < EDIM / 32; q++) {
            int k = lane + q * 32;
            s = fmaf(Zs[i][k], Zs[j][k], s);
        }
#pragma unroll
        for (int off = 16; off > 0; off >>= 1)
            s += __shfl_down_sync(0xffffffffu, s, off);
        if (lane == 0) xrow[p] = s;
    }

    // dense tail + zero pad
    if (tid < EDIM) xrow[N_PAIRS + tid] = Zs[26][tid];
    if (tid == 128) xrow[TOP_IN] = 0.0f;  // padded col 479
}

// ---------------- Final layer: (B,256)@(256,1)+bo -> sigmoid --------------
__global__ __launch_bounds__(256)
void final_kernel(const float* __restrict__ Wo, const float* __restrict__ bo,
                  float* __restrict__ out) {
    __shared__ float ws[256];
    const int tid = threadIdx.x;
    ws[tid] = Wo[tid];
    __syncthreads();

    const int lane = tid & 31;
    const int warp = tid >> 5;
    const int row = blockIdx.x * 8 + warp;

    const float* a = g_t4 + (size_t)row * 256;
    float s = 0.0f;
#pragma unroll
    for (int q = 0; q < 8; q++) {
        int k = lane + q * 32;
        s = fmaf(a[k], ws[k], s);
    }
#pragma unroll
    for (int off = 16; off > 0; off >>= 1)
        s += __shfl_down_sync(0xffffffffu, s, off);
    if (lane == 0) {
        float z = s + bo[0];
        out[row] = 1.0f / (1.0f + __expf(-z));
    }
}

// ---------------- Launch ---------------------------------------------------
extern "C" void kernel_launch(void* const* d_in, const int* in_sizes, int n_in,
                              void* d_out, int out_size) {
    const float* dense_x = (const float*)d_in[0];
    const void*  cat_idx = d_in[1];               // dtype detected on device
    const float* emb     = (const float*)d_in[2];
    const float* Wd1 = (const float*)d_in[3];
    const float* bd1 = (const float*)d_in[4];
    const float* Wd2 = (const float*)d_in[5];
    const float* bd2 = (const float*)d_in[6];
    const float* Wdf = (const float*)d_in[7];
    const float* bdf = (const float*)d_in[8];
    const float* Wt1 = (const float*)d_in[9];
    const float* bt1 = (const float*)d_in[10];
    const float* Wt2 = (const float*)d_in[11];
    const float* bt2 = (const float*)d_in[12];
    const float* Wt3 = (const float*)d_in[13];
    const float* bt3 = (const float*)d_in[14];
    const float* Wt4 = (const float*)d_in[15];
    const float* bt4 = (const float*)d_in[16];
    const float* Wo  = (const float*)d_in[17];
    const float* bo  = (const float*)d_in[18];
    float* out = (float*)d_out;

    float *h1, *h2, *x, *t1, *t2, *t3, *t4, *Wt1p;
    cudaGetSymbolAddress((void**)&h1,   g_h1);
    cudaGetSymbolAddress((void**)&h2,   g_h2);
    cudaGetSymbolAddress((void**)&x,    g_x);
    cudaGetSymbolAddress((void**)&t1,   g_t1);
    cudaGetSymbolAddress((void**)&t2,   g_t2);
    cudaGetSymbolAddress((void**)&t3,   g_t3);
    cudaGetSymbolAddress((void**)&t4,   g_t4);
    cudaGetSymbolAddress((void**)&Wt1p, g_Wt1p);

    // cat_idx dtype detection (int32 vs int64), fully in-stream
    idx_reset_kernel<<<1, 1>>>();
    idx_detect_kernel<<<16, 256>>>((const int*)cat_idx);  // 4096 odd words

    // Wt1 zero-pad to K=480
    pad_wt1_kernel<<<(TOP_IN_PAD * 1024 + 255) / 256, 256>>>(Wt1);

    // Bottom MLP
    bottom1_kernel<<<BATCH, 512>>>(dense_x, Wd1, bd1);
    // h2 = relu(h1 @ Wd2 + bd2): M=16384, N=256, K=512
    sgemm_bias_act<true><<<dim3(256 / BN, BATCH / BM), 256>>>(h1, Wd2, bd2, h2, 256, 512, 512);
    // dense = relu(h2 @ Wdf + bdf): N=128, K=256
    {
        float* densep;
        cudaGetSymbolAddress((void**)&densep, g_dense);
        sgemm_bias_act<true><<<dim3(128 / BN, BATCH / BM), 256>>>(h2, Wdf, bdf, densep, 128, 256, 256);
    }

    // Gather + interactions -> x (stride 480)
    interact_kernel<<<BATCH, 256>>>(cat_idx, emb);

    // Top MLP
    sgemm_bias_act<true><<<dim3(1024 / BN, BATCH / BM), 256>>>(x,  Wt1p, bt1, t1, 1024, TOP_IN_PAD, TOP_IN_PAD);
    sgemm_bias_act<true><<<dim3(1024 / BN, BATCH / BM), 256>>>(t1, Wt2,  bt2, t2, 1024, 1024, 1024);
    sgemm_bias_act<true><<<dim3(512  / BN, BATCH / BM), 256>>>(t2, Wt3,  bt3, t3, 512, 1024, 1024);
    sgemm_bias_act<true><<<dim3(256  / BN, BATCH / BM), 256>>>(t3, Wt4,  bt4, t4, 256, 512, 512);

    // Sigmoid head
    final_kernel<<<BATCH / 8, 256>>>(Wo, bo, out);
}

// round 7
// speedup vs baseline: 1.9507x; 1.9507x over previous
#include <cuda_runtime.h>
#include <cuda_bf16.h>
#include <math.h>

// ---------------- Problem constants ----------------
#define BATCH   16384
#define N_CAT   26
#define N_CONT  13
#define EDIM    128
#define VOCAB   100000
#define N_PAIRS 351            // 27*26/2
#define TOP_IN  479            // 351 + 128
#define TOP_IN_PAD 480

// ---------------- Scratch (device globals; allocation-free) ----------------
__device__ float g_h1[BATCH * 512];
__device__ float g_h2[BATCH * 256];
__device__ float g_dense[BATCH * EDIM];
__device__ float g_x[BATCH * TOP_IN_PAD];
__device__ float g_t1[BATCH * 1024];
__device__ float g_t2[BATCH * 1024];
__device__ float g_t3[BATCH * 512];
__device__ float g_t4[BATCH * 256];
__device__ float g_Wt1p[TOP_IN_PAD * 1024];
__device__ int   g_idx_is64;    // 1 if cat_idx buffer is int64, 0 if int32

// ---------------- cat_idx dtype detection ---------------------------------
__global__ void idx_reset_kernel() { g_idx_is64 = 1; }

__global__ void idx_detect_kernel(const int* __restrict__ cat_raw) {
    int i = blockIdx.x * 256 + threadIdx.x;
    int w = cat_raw[2 * i + 1];
    if (w != 0) g_idx_is64 = 0;                  // int32 data detected
}

// ---------------- Wt1 zero-pad (479x1024 -> 480x1024) ----------------
__global__ void pad_wt1_kernel(const float* __restrict__ Wt1) {
    int i = blockIdx.x * 256 + threadIdx.x;
    if (i >= TOP_IN_PAD * 1024) return;
    int r = i >> 10;
    int c = i & 1023;
    g_Wt1p[i] = (r < TOP_IN) ? Wt1[r * 1024 + c] : 0.0f;
}

// ---------------- Bottom MLP layer 1: (B,13) @ (13,512) + b, relu ----------
__global__ void bottom1_kernel(const float* __restrict__ x,
                               const float* __restrict__ W,
                               const float* __restrict__ b) {
    __shared__ float xs[N_CONT];
    int batch = blockIdx.x;
    int n = threadIdx.x;
    if (n < N_CONT) xs[n] = x[batch * N_CONT + n];
    __syncthreads();
    float acc = b[n];
#pragma unroll
    for (int k = 0; k < N_CONT; k++)
        acc += xs[k] * W[k * 512 + n];
    g_h1[(size_t)batch * 512 + n] = fmaxf(acc, 0.0f);
}

// ---------------- tf32 tensor-core GEMM: C = relu(A @ B + bias) ------------
// A: M x K row-major (lda = K). B: K x N row-major. C: M x N.
// Block tile 128x128x16, 8 warps (4 M x 2 N), warp tile 32x64,
// mma.sync.m16n8k8 tf32 with fp32 accumulation.
// Requires: M%128==0, N%128==0, K%16==0.

__device__ __forceinline__ unsigned cvt_tf32(float x) {
    unsigned r;
    asm("cvt.rna.tf32.f32 %0, %1;" : "=r"(r) : "f"(x));
    return r;
}

__device__ __forceinline__ void mma_tf32(float c[4], const unsigned a[4],
                                         const unsigned b[2]) {
    asm volatile(
        "mma.sync.aligned.m16n8k8.row.col.f32.tf32.tf32.f32 "
        "{%0,%1,%2,%3}, {%4,%5,%6,%7}, {%8,%9}, {%0,%1,%2,%3};"
        : "+f"(c[0]), "+f"(c[1]), "+f"(c[2]), "+f"(c[3])
        : "r"(a[0]), "r"(a[1]), "r"(a[2]), "r"(a[3]),
          "r"(b[0]), "r"(b[1]));
}

#define AS_STRIDE 20   // 128 rows x 20 floats: conflict-free fragment reads

template<bool RELU>
__global__ __launch_bounds__(256, 2)
void mma_gemm(const float* __restrict__ A, const float* __restrict__ B,
              const float* __restrict__ bias, float* __restrict__ C,
              int N, int K) {
    __shared__ float As[128 * AS_STRIDE];   // [m][k], stride 20
    __shared__ float Bs[16 * 128];          // [k][n ^ ((k&3)*8)]

    const int tid  = threadIdx.x;
    const int lane = tid & 31;
    const int warp = tid >> 5;
    const int wm   = warp & 3;   // 0..3  (M)
    const int wn   = warp >> 2;  // 0..1  (N)
    const int lr   = lane >> 2;  // 0..7
    const int lc   = lane & 3;   // 0..3

    const int bx = blockIdx.x;   // N tile
    const int by = blockIdx.y;   // M tile

    // Loader mapping (2 float4 per thread per tile)
    // A: i in [0,512): m = i>>2, kc = (i&3)<<2
    // B: i in [0,512): k = i>>5, nc = (i&31)<<2
    const int am0 = tid >> 2,        akc0 = (tid & 3) << 2;
    const int am1 = (tid + 256) >> 2, akc1 = akc0;  // same kc pattern
    const int bk0 = tid >> 5,        bnc  = (tid & 31) << 2;
    const int bk1 = bk0 + 8;

    const float* Abase = A + (size_t)(by * 128) * K;
    const float* Bbase = B + bx * 128;

    float acc[2][8][4];
#pragma unroll
    for (int mt = 0; mt < 2; mt++)
#pragma unroll
        for (int nt = 0; nt < 8; nt++)
#pragma unroll
            for (int q = 0; q < 4; q++) acc[mt][nt][q] = 0.0f;

    // Prologue: fetch first tiles into registers
    float4 a4[2], b4[2];
    a4[0] = *(const float4*)(Abase + (size_t)am0 * K + akc0);
    a4[1] = *(const float4*)(Abase + (size_t)am1 * K + akc1);
    b4[0] = *(const float4*)(Bbase + (size_t)bk0 * N + bnc);
    b4[1] = *(const float4*)(Bbase + (size_t)bk1 * N + bnc);

    const int nIter = K >> 4;
    for (int it = 0; it < nIter; it++) {
        // Store staged tile to smem
        *(float4*)&As[am0 * AS_STRIDE + akc0] = a4[0];
        *(float4*)&As[am1 * AS_STRIDE + akc1] = a4[1];
        *(float4*)&Bs[bk0 * 128 + (bnc ^ ((bk0 & 3) * 8))] = b4[0];
        *(float4*)&Bs[bk1 * 128 + (bnc ^ ((bk1 & 3) * 8))] = b4[1];
        __syncthreads();

        // Prefetch next tile (overlaps with MMA below)
        if (it + 1 < nIter) {
            int k0 = (it + 1) << 4;
            a4[0] = *(const float4*)(Abase + (size_t)am0 * K + k0 + akc0);
            a4[1] = *(const float4*)(Abase + (size_t)am1 * K + k0 + akc1);
            b4[0] = *(const float4*)(Bbase + (size_t)(k0 + bk0) * N + bnc);
            b4[1] = *(const float4*)(Bbase + (size_t)(k0 + bk1) * N + bnc);
        }

#pragma unroll
        for (int ks = 0; ks < 2; ks++) {
            unsigned afr[2][4], bfr[8][2];
#pragma unroll
            for (int mt = 0; mt < 2; mt++) {
                int r = wm * 32 + mt * 16 + lr;
                int c = ks * 8 + lc;
                afr[mt][0] = cvt_tf32(As[r * AS_STRIDE + c]);
                afr[mt][1] = cvt_tf32(As[(r + 8) * AS_STRIDE + c]);
                afr[mt][2] = cvt_tf32(As[r * AS_STRIDE + c + 4]);
                afr[mt][3] = cvt_tf32(As[(r + 8) * AS_STRIDE + c + 4]);
            }
#pragma unroll
            for (int nt = 0; nt < 8; nt++) {
                int n = wn * 64 + nt * 8 + lr;
                int k = ks * 8 + lc;
                int sw = lc * 8;
                bfr[nt][0] = cvt_tf32(Bs[k * 128 + (n ^ sw)]);
                bfr[nt][1] = cvt_tf32(Bs[(k + 4) * 128 + (n ^ sw)]);
            }
#pragma unroll
            for (int mt = 0; mt < 2; mt++)
#pragma unroll
                for (int nt = 0; nt < 8; nt++)
                    mma_tf32(acc[mt][nt], afr[mt], bfr[nt]);
        }
        __syncthreads();
    }

    // Epilogue: bias + relu, float2 stores
#pragma unroll
    for (int mt = 0; mt < 2; mt++) {
        int r0 = by * 128 + wm * 32 + mt * 16 + lr;
#pragma unroll
        for (int nt = 0; nt < 8; nt++) {
            int col = bx * 128 + wn * 64 + nt * 8 + 2 * lc;
            float bv0 = __ldg(&bias[col]);
            float bv1 = __ldg(&bias[col + 1]);
            float2 v0, v1;
            v0.x = acc[mt][nt][0] + bv0;
            v0.y = acc[mt][nt][1] + bv1;
            v1.x = acc[mt][nt][2] + bv0;
            v1.y = acc[mt][nt][3] + bv1;
            if (RELU) {
                v0.x = fmaxf(v0.x, 0.0f); v0.y = fmaxf(v0.y, 0.0f);
                v1.x = fmaxf(v1.x, 0.0f); v1.y = fmaxf(v1.y, 0.0f);
            }
            *(float2*)(C + (size_t)r0 * N + col)       = v0;
            *(float2*)(C + (size_t)(r0 + 8) * N + col) = v1;
        }
    }
}

// ---------------- Gather + pairwise interaction ---------------------------
__global__ __launch_bounds__(256)
void interact_kernel(const void* __restrict__ cat_idx,
                     const float* __restrict__ emb) {
    __shared__ float Zs[27][EDIM];
    __shared__ int idxs[N_CAT];

    const int b = blockIdx.x;
    const int tid = threadIdx.x;
    const int lane = tid & 31;
    const int warp = tid >> 5;

    if (tid < N_CAT) {
        long long v;
        if (g_idx_is64) {
            v = ((const long long*)cat_idx)[(size_t)b * N_CAT + tid];
        } else {
            v = (long long)((const int*)cat_idx)[(size_t)b * N_CAT + tid];
        }
        if (v < 0) v = 0;
        if (v >= VOCAB) v = VOCAB - 1;
        idxs[tid] = (int)v;
    }
    __syncthreads();

    for (int i = tid; i < 27 * EDIM; i += 256) {
        int r = i >> 7;
        int c = i & 127;
        float v;
        if (r < N_CAT) {
            size_t off = (size_t)r * (VOCAB * EDIM) + (size_t)idxs[r] * EDIM + c;
            v = emb[off];
        } else {
            v = g_dense[(size_t)b * EDIM + c];
        }
        Zs[r][c] = v;
    }
    __syncthreads();

    float* xrow = g_x + (size_t)b * TOP_IN_PAD;

    for (int p = warp; p < N_PAIRS; p += 8) {
        int i = 0, rem = p;
        while (rem >= (N_CAT - i)) { rem -= (N_CAT - i); i++; }
        int j = i + 1 + rem;

        float s = 0.0f;
#pragma unroll
        for (int q = 0; q < EDIM / 32; q++) {
            int k = lane + q * 32;
            s = fmaf(Zs[i][k], Zs[j][k], s);
        }
#pragma unroll
        for (int off = 16; off > 0; off >>= 1)
            s += __shfl_down_sync(0xffffffffu, s, off);
        if (lane == 0) xrow[p] = s;
    }

    if (tid < EDIM) xrow[N_PAIRS + tid] = Zs[26][tid];
    if (tid == 128) xrow[TOP_IN] = 0.0f;
}

// ---------------- Final layer: (B,256)@(256,1)+bo -> sigmoid --------------
__global__ __launch_bounds__(256)
void final_kernel(const float* __restrict__ Wo, const float* __restrict__ bo,
                  float* __restrict__ out) {
    __shared__ float ws[256];
    const int tid = threadIdx.x;
    ws[tid] = Wo[tid];
    __syncthreads();

    const int lane = tid & 31;
    const int warp = tid >> 5;
    const int row = blockIdx.x * 8 + warp;

    const float* a = g_t4 + (size_t)row * 256;
    float s = 0.0f;
#pragma unroll
    for (int q = 0; q < 8; q++) {
        int k = lane + q * 32;
        s = fmaf(a[k], ws[k], s);
    }
#pragma unroll
    for (int off = 16; off > 0; off >>= 1)
        s += __shfl_down_sync(0xffffffffu, s, off);
    if (lane == 0) {
        float z = s + bo[0];
        out[row] = 1.0f / (1.0f + __expf(-z));
    }
}

// ---------------- Launch ---------------------------------------------------
extern "C" void kernel_launch(void* const* d_in, const int* in_sizes, int n_in,
                              void* d_out, int out_size) {
    const float* dense_x = (const float*)d_in[0];
    const void*  cat_idx = d_in[1];
    const float* emb     = (const float*)d_in[2];
    const float* Wd1 = (const float*)d_in[3];
    const float* bd1 = (const float*)d_in[4];
    const float* Wd2 = (const float*)d_in[5];
    const float* bd2 = (const float*)d_in[6];
    const float* Wdf = (const float*)d_in[7];
    const float* bdf = (const float*)d_in[8];
    const float* Wt1 = (const float*)d_in[9];
    const float* bt1 = (const float*)d_in[10];
    const float* Wt2 = (const float*)d_in[11];
    const float* bt2 = (const float*)d_in[12];
    const float* Wt3 = (const float*)d_in[13];
    const float* bt3 = (const float*)d_in[14];
    const float* Wt4 = (const float*)d_in[15];
    const float* bt4 = (const float*)d_in[16];
    const float* Wo  = (const float*)d_in[17];
    const float* bo  = (const float*)d_in[18];
    float* out = (float*)d_out;

    float *h1, *h2, *dense, *x, *t1, *t2, *t3, *t4, *Wt1p;
    cudaGetSymbolAddress((void**)&h1,    g_h1);
    cudaGetSymbolAddress((void**)&h2,    g_h2);
    cudaGetSymbolAddress((void**)&dense, g_dense);
    cudaGetSymbolAddress((void**)&x,     g_x);
    cudaGetSymbolAddress((void**)&t1,    g_t1);
    cudaGetSymbolAddress((void**)&t2,    g_t2);
    cudaGetSymbolAddress((void**)&t3,    g_t3);
    cudaGetSymbolAddress((void**)&t4,    g_t4);
    cudaGetSymbolAddress((void**)&Wt1p,  g_Wt1p);

    // cat_idx dtype detection (int32 vs int64), fully in-stream
    idx_reset_kernel<<<1, 1>>>();
    idx_detect_kernel<<<16, 256>>>((const int*)cat_idx);

    // Wt1 zero-pad to K=480
    pad_wt1_kernel<<<(TOP_IN_PAD * 1024 + 255) / 256, 256>>>(Wt1);

    // Bottom MLP
    bottom1_kernel<<<BATCH, 512>>>(dense_x, Wd1, bd1);
    // h2 = relu(h1 @ Wd2 + bd2): N=256, K=512
    mma_gemm<true><<<dim3(256 / 128, BATCH / 128), 256>>>(h1, Wd2, bd2, h2, 256, 512);
    // dense = relu(h2 @ Wdf + bdf): N=128, K=256
    mma_gemm<true><<<dim3(128 / 128, BATCH / 128), 256>>>(h2, Wdf, bdf, dense, 128, 256);

    // Gather + interactions -> x (stride 480)
    interact_kernel<<<BATCH, 256>>>(cat_idx, emb);

    // Top MLP (tf32 tensor cores)
    mma_gemm<true><<<dim3(1024 / 128, BATCH / 128), 256>>>(x,  Wt1p, bt1, t1, 1024, TOP_IN_PAD);
    mma_gemm<true><<<dim3(1024 / 128, BATCH / 128), 256>>>(t1, Wt2,  bt2, t2, 1024, 1024);
    mma_gemm<true><<<dim3(512  / 128, BATCH / 128), 256>>>(t2, Wt3,  bt3, t3, 512, 1024);
    mma_gemm<true><<<dim3(256  / 128, BATCH / 128), 256>>>(t3, Wt4,  bt4, t4, 256, 512);

    // Sigmoid head
    final_kernel<<<BATCH / 8, 256>>>(Wo, bo, out);
}